// round 1
// baseline (speedup 1.0000x reference)
#include <cuda_runtime.h>

// Problem constants
#define T_    256
#define B_    256
#define H_    1024
#define E_    300
#define FEAT  319
#define FEATP 320          // padded to multiple of 32 for float4 K-tiling
#define C_    13
#define G4H   4096
#define M_    (T_ * B_)    // 65536 rows total

// -------- scratch (static device globals; no allocation anywhere) --------
__device__ float g_X[(size_t)M_ * FEATP];        //  83.9 MB  concat(emb,casing,pos), padded
__device__ float g_wi0p[(size_t)G4H * FEATP];    //   5.2 MB  wi0 padded to K=320
__device__ float g_pre0[(size_t)M_ * G4H];       //   1.07 GB i2h preactivations, bias folded
__device__ float g_h0[(size_t)M_ * H_];          // 268.4 MB  layer0 h, all timesteps
__device__ float g_c0[(size_t)M_ * H_];          // 268.4 MB  layer0 c, all timesteps
__device__ float g_h1[(size_t)M_ * H_];          // 268.4 MB  layer1 h, all timesteps

__device__ __forceinline__ float sigmoidf_(float x) {
    return 1.0f / (1.0f + __expf(-x));
}

// ===========================================================================
// Kernel 1: build X = [emb_table[tokens] | casing | pos | 0pad] per row
// ===========================================================================
__global__ void k_build_x(const int* __restrict__ tokens,
                          const float* __restrict__ casing,
                          const float* __restrict__ pos,
                          const float* __restrict__ emb) {
    int m = blockIdx.x;                    // 0..65535  (m = t*B + b)
    int tok = tokens[m];
    const float* erow = emb + (size_t)tok * E_;
    float* xrow = g_X + (size_t)m * FEATP;
    for (int k = threadIdx.x; k < FEATP; k += blockDim.x) {
        float v;
        if (k < E_)            v = erow[k];
        else if (k < E_ + 7)   v = casing[m * 7 + (k - E_)];
        else if (k < FEAT)     v = pos[m * 12 + (k - E_ - 7)];
        else                   v = 0.0f;
        xrow[k] = v;
    }
}

// ===========================================================================
// Kernel 2: pad wi0 [4096,319] -> [4096,320]
// ===========================================================================
__global__ void k_pad_wi0(const float* __restrict__ wi0) {
    int j = blockIdx.x;                    // 0..4095
    for (int k = threadIdx.x; k < FEATP; k += blockDim.x)
        g_wi0p[(size_t)j * FEATP + k] = (k < FEAT) ? wi0[(size_t)j * FEAT + k] : 0.0f;
}

// ===========================================================================
// Kernel 3: pre0 = X @ wi0p^T + (bi0 + bh0)    [65536 x 4096], K = 320
// NT layout: both A rows and W rows contiguous along K.
// BM=128, BN=64, BK=32, 256 threads, thread tile 8x4.
// ===========================================================================
#define G1_BM 128
#define G1_BN 64
#define G1_BK 32
__global__ __launch_bounds__(256) void k_gemm_pre0(const float* __restrict__ bi0,
                                                   const float* __restrict__ bh0) {
    __shared__ float As[G1_BK][G1_BM + 4];   // [32][132]
    __shared__ float Bs[G1_BK][G1_BN + 4];   // [32][68]

    const int m0 = blockIdx.y * G1_BM;
    const int n0 = blockIdx.x * G1_BN;
    const int tid = threadIdx.x;
    const int tx = tid & 15;     // 16 -> 4 cols each = 64
    const int ty = tid >> 4;     // 16 -> 8 rows each = 128

    float acc[8][4];
#pragma unroll
    for (int i = 0; i < 8; i++)
#pragma unroll
        for (int j = 0; j < 4; j++) acc[i][j] = 0.0f;

    for (int k0 = 0; k0 < FEATP; k0 += G1_BK) {
        // A tile: 128x32 = 1024 float4, 4 per thread
#pragma unroll
        for (int it = 0; it < 4; it++) {
            int i = tid + it * 256;
            int row = i >> 3, kq = i & 7;
            float4 v = *(const float4*)(g_X + (size_t)(m0 + row) * FEATP + k0 + kq * 4);
            As[kq * 4 + 0][row] = v.x; As[kq * 4 + 1][row] = v.y;
            As[kq * 4 + 2][row] = v.z; As[kq * 4 + 3][row] = v.w;
        }
        // B tile: 64x32 = 512 float4, 2 per thread
#pragma unroll
        for (int it = 0; it < 2; it++) {
            int i = tid + it * 256;
            int row = i >> 3, kq = i & 7;
            float4 v = *(const float4*)(g_wi0p + (size_t)(n0 + row) * FEATP + k0 + kq * 4);
            Bs[kq * 4 + 0][row] = v.x; Bs[kq * 4 + 1][row] = v.y;
            Bs[kq * 4 + 2][row] = v.z; Bs[kq * 4 + 3][row] = v.w;
        }
        __syncthreads();
#pragma unroll
        for (int kk = 0; kk < G1_BK; kk++) {
            float4 a0 = *(const float4*)&As[kk][ty * 8 + 0];
            float4 a1 = *(const float4*)&As[kk][ty * 8 + 4];
            float4 b  = *(const float4*)&Bs[kk][tx * 4];
            float a[8] = {a0.x, a0.y, a0.z, a0.w, a1.x, a1.y, a1.z, a1.w};
            float bb[4] = {b.x, b.y, b.z, b.w};
#pragma unroll
            for (int i = 0; i < 8; i++)
#pragma unroll
                for (int j = 0; j < 4; j++) acc[i][j] += a[i] * bb[j];
        }
        __syncthreads();
    }

    const int n = n0 + tx * 4;
    float bias[4];
#pragma unroll
    for (int j = 0; j < 4; j++) bias[j] = bi0[n + j] + bh0[n + j];
#pragma unroll
    for (int i = 0; i < 8; i++) {
        int m = m0 + ty * 8 + i;
        float4 r;
        r.x = acc[i][0] + bias[0];
        r.y = acc[i][1] + bias[1];
        r.z = acc[i][2] + bias[2];
        r.w = acc[i][3] + bias[3];
        *(float4*)(g_pre0 + (size_t)m * G4H + n) = r;
    }
}

// ===========================================================================
// Kernel 4: layer-0 LSTM step (sequential over t).
// Gate-aligned tiling: CTA computes cols [n0,n0+32) at all 4 gate offsets,
// fusing gates + c/h update into the GEMM epilogue.
// pre[m, g*H+n] = pre0[t][m, g*H+n] + sum_k h_prev[m,k] * wh0[g*H+n, k]
// BM=64 (batch), BN=32 per gate, BK=32, 256 threads -> grid 32 x 4 = 128 CTAs.
// ===========================================================================
#define L0_BM 64
#define L0_BN 32
#define L0_BK 32
__global__ __launch_bounds__(256) void k_lstm0_step(int t,
                                                    const float* __restrict__ h_init0,
                                                    const float* __restrict__ c_init0,
                                                    const float* __restrict__ wh0) {
    __shared__ float As[L0_BK][L0_BM + 4];        // [32][68]
    __shared__ float Bs[4][L0_BK][L0_BN + 4];     // [4][32][36]

    const float* hprev = (t == 0) ? h_init0 : (g_h0 + (size_t)(t - 1) * B_ * H_);
    const float* cprev = (t == 0) ? c_init0 : (g_c0 + (size_t)(t - 1) * B_ * H_);
    const float* pre0t = g_pre0 + (size_t)t * B_ * G4H;
    float* hout = g_h0 + (size_t)t * B_ * H_;
    float* cout = g_c0 + (size_t)t * B_ * H_;

    const int m0 = blockIdx.y * L0_BM;
    const int n0 = blockIdx.x * L0_BN;
    const int tid = threadIdx.x;
    const int tx = tid & 7;      // 8  -> 4 cols each = 32
    const int ty = tid >> 3;     // 32 -> 2 rows each = 64

    float acc[4][2][4];
#pragma unroll
    for (int g = 0; g < 4; g++)
#pragma unroll
        for (int i = 0; i < 2; i++)
#pragma unroll
            for (int j = 0; j < 4; j++) acc[g][i][j] = 0.0f;

    for (int k0 = 0; k0 < H_; k0 += L0_BK) {
        // A tile: 64x32 = 512 float4, 2 per thread
#pragma unroll
        for (int it = 0; it < 2; it++) {
            int i = tid + it * 256;
            int row = i >> 3, kq = i & 7;
            float4 v = *(const float4*)(hprev + (size_t)(m0 + row) * H_ + k0 + kq * 4);
            As[kq * 4 + 0][row] = v.x; As[kq * 4 + 1][row] = v.y;
            As[kq * 4 + 2][row] = v.z; As[kq * 4 + 3][row] = v.w;
        }
        // B tiles: 4 gates x 32x32 = 1024 float4, 4 per thread
#pragma unroll
        for (int it = 0; it < 4; it++) {
            int i = tid + it * 256;
            int gt = i >> 8;             // 0..3
            int r = (i & 255) >> 3;      // 0..31
            int kq = i & 7;
            float4 v = *(const float4*)(wh0 + (size_t)(gt * H_ + n0 + r) * H_ + k0 + kq * 4);
            Bs[gt][kq * 4 + 0][r] = v.x; Bs[gt][kq * 4 + 1][r] = v.y;
            Bs[gt][kq * 4 + 2][r] = v.z; Bs[gt][kq * 4 + 3][r] = v.w;
        }
        __syncthreads();
#pragma unroll
        for (int kk = 0; kk < L0_BK; kk++) {
            float a0 = As[kk][ty * 2 + 0];
            float a1 = As[kk][ty * 2 + 1];
#pragma unroll
            for (int g = 0; g < 4; g++) {
                float4 b = *(const float4*)&Bs[g][kk][tx * 4];
                acc[g][0][0] += a0 * b.x; acc[g][0][1] += a0 * b.y;
                acc[g][0][2] += a0 * b.z; acc[g][0][3] += a0 * b.w;
                acc[g][1][0] += a1 * b.x; acc[g][1][1] += a1 * b.y;
                acc[g][1][2] += a1 * b.z; acc[g][1][3] += a1 * b.w;
            }
        }
        __syncthreads();
    }

#pragma unroll
    for (int i = 0; i < 2; i++) {
        int m = m0 + ty * 2 + i;
        const float* p = pre0t + (size_t)m * G4H;
#pragma unroll
        for (int j = 0; j < 4; j++) {
            int nn = n0 + tx * 4 + j;
            float pi = acc[0][i][j] + p[nn];
            float pf = acc[1][i][j] + p[H_ + nn];
            float po = acc[2][i][j] + p[2 * H_ + nn];
            float pg = acc[3][i][j] + p[3 * H_ + nn];
            float ig = sigmoidf_(pi);
            float fg = sigmoidf_(pf);
            float og = sigmoidf_(po);
            float gg = tanhf(pg);
            float c = fg * cprev[(size_t)m * H_ + nn] + ig * gg;
            float h = og * tanhf(c);
            hout[(size_t)m * H_ + nn] = h;
            cout[(size_t)m * H_ + nn] = c;
        }
    }
}

// ===========================================================================
// Kernel 5: layer-1, batch-parallel over all T*B rows (stateless in time).
// pre1[m, g*H+n] = h0[m]@wi1[g*H+n]^T + h0[mflip]@wh1[g*H+n]^T + bi1 + bh1
// where mflip = flip of batch index within the timestep.
// c1 = f * c0[mflip] + i * g ; h1 = o * tanh(c1). Only h1 is stored.
// BM=128, BN=32 per gate, BK=32, 256 threads -> 512 x 32 = 16384 CTAs.
// ===========================================================================
#define L1_BM 128
#define L1_BN 32
#define L1_BK 32
__global__ __launch_bounds__(256, 2) void k_lstm1(const float* __restrict__ wi1,
                                                  const float* __restrict__ wh1,
                                                  const float* __restrict__ bi1,
                                                  const float* __restrict__ bh1) {
    __shared__ float As[L1_BK][L1_BM + 4];        // [32][132]
    __shared__ float Bs[4][L1_BK][L1_BN + 4];     // [4][32][36]

    const int m0 = blockIdx.y * L1_BM;
    const int n0 = blockIdx.x * L1_BN;
    const int tid = threadIdx.x;
    const int tx = tid & 7;      // 8  -> 4 cols each = 32
    const int ty = tid >> 3;     // 32 -> 4 rows each = 128

    float acc[4][4][4];
#pragma unroll
    for (int g = 0; g < 4; g++)
#pragma unroll
        for (int i = 0; i < 4; i++)
#pragma unroll
            for (int j = 0; j < 4; j++) acc[g][i][j] = 0.0f;

    for (int kt = 0; kt < 2 * H_; kt += L1_BK) {
        const bool second = (kt >= H_);
        const int kk0 = kt & (H_ - 1);
        const float* W = second ? wh1 : wi1;
        // A tile: 128x32 = 1024 float4, 4 per thread; second half uses batch-flipped rows
#pragma unroll
        for (int it = 0; it < 4; it++) {
            int i = tid + it * 256;
            int row = i >> 3, kq = i & 7;
            int m = m0 + row;
            int bq = m & 255;
            int msel = second ? (m - bq + (255 - bq)) : m;
            float4 v = *(const float4*)(g_h0 + (size_t)msel * H_ + kk0 + kq * 4);
            As[kq * 4 + 0][row] = v.x; As[kq * 4 + 1][row] = v.y;
            As[kq * 4 + 2][row] = v.z; As[kq * 4 + 3][row] = v.w;
        }
        // B tiles: 4 gates x 32x32 = 1024 float4, 4 per thread
#pragma unroll
        for (int it = 0; it < 4; it++) {
            int i = tid + it * 256;
            int gt = i >> 8;
            int r = (i & 255) >> 3;
            int kq = i & 7;
            float4 v = *(const float4*)(W + (size_t)(gt * H_ + n0 + r) * H_ + kk0 + kq * 4);
            Bs[gt][kq * 4 + 0][r] = v.x; Bs[gt][kq * 4 + 1][r] = v.y;
            Bs[gt][kq * 4 + 2][r] = v.z; Bs[gt][kq * 4 + 3][r] = v.w;
        }
        __syncthreads();
#pragma unroll
        for (int kk = 0; kk < L1_BK; kk++) {
            float4 av = *(const float4*)&As[kk][ty * 4];
            float a[4] = {av.x, av.y, av.z, av.w};
#pragma unroll
            for (int g = 0; g < 4; g++) {
                float4 b = *(const float4*)&Bs[g][kk][tx * 4];
                float bb[4] = {b.x, b.y, b.z, b.w};
#pragma unroll
                for (int i = 0; i < 4; i++)
#pragma unroll
                    for (int j = 0; j < 4; j++) acc[g][i][j] += a[i] * bb[j];
            }
        }
        __syncthreads();
    }

    const int n = n0 + tx * 4;
    float bsum[4][4];
#pragma unroll
    for (int g = 0; g < 4; g++)
#pragma unroll
        for (int j = 0; j < 4; j++) bsum[g][j] = bi1[g * H_ + n + j] + bh1[g * H_ + n + j];

#pragma unroll
    for (int i = 0; i < 4; i++) {
        int m = m0 + ty * 4 + i;
        int bq = m & 255;
        int mflip = m - bq + (255 - bq);
        float4 r;
        float hv[4];
#pragma unroll
        for (int j = 0; j < 4; j++) {
            int nn = n + j;
            float pi = acc[0][i][j] + bsum[0][j];
            float pf = acc[1][i][j] + bsum[1][j];
            float po = acc[2][i][j] + bsum[2][j];
            float pg = acc[3][i][j] + bsum[3][j];
            float ig = sigmoidf_(pi);
            float fg = sigmoidf_(pf);
            float og = sigmoidf_(po);
            float gg = tanhf(pg);
            float c = fg * g_c0[(size_t)mflip * H_ + nn] + ig * gg;
            hv[j] = og * tanhf(c);
        }
        r.x = hv[0]; r.y = hv[1]; r.z = hv[2]; r.w = hv[3];
        *(float4*)(g_h1 + (size_t)m * H_ + n) = r;
    }
}

// ===========================================================================
// Kernel 6: decode. out[m, c] = [h0[m] | h1[m]] . dec_w[c] + dec_b[c]
// Warp per row; float4 loads; 13 warp reductions.
// ===========================================================================
__global__ __launch_bounds__(256) void k_decode(const float* __restrict__ dec_w,
                                                const float* __restrict__ dec_b,
                                                float* __restrict__ out) {
    int gwarp = (blockIdx.x * blockDim.x + threadIdx.x) >> 5;
    int lane = threadIdx.x & 31;
    if (gwarp >= M_) return;
    const float* h0r = g_h0 + (size_t)gwarp * H_;
    const float* h1r = g_h1 + (size_t)gwarp * H_;

    float acc[C_];
#pragma unroll
    for (int c = 0; c < C_; c++) acc[c] = 0.0f;

    for (int k = lane * 4; k < H_; k += 128) {
        float4 v0 = *(const float4*)(h0r + k);
        float4 v1 = *(const float4*)(h1r + k);
#pragma unroll
        for (int c = 0; c < C_; c++) {
            const float* w = dec_w + (size_t)c * 2 * H_;
            float4 w0 = *(const float4*)(w + k);
            float4 w1 = *(const float4*)(w + H_ + k);
            acc[c] += v0.x * w0.x + v0.y * w0.y + v0.z * w0.z + v0.w * w0.w
                    + v1.x * w1.x + v1.y * w1.y + v1.z * w1.z + v1.w * w1.w;
        }
    }
#pragma unroll
    for (int c = 0; c < C_; c++) {
#pragma unroll
        for (int off = 16; off > 0; off >>= 1)
            acc[c] += __shfl_down_sync(0xFFFFFFFFu, acc[c], off);
    }
    if (lane == 0) {
#pragma unroll
        for (int c = 0; c < C_; c++)
            out[(size_t)gwarp * C_ + c] = acc[c] + dec_b[c];
    }
}

// ===========================================================================
// Launch
// ===========================================================================
extern "C" void kernel_launch(void* const* d_in, const int* in_sizes, int n_in,
                              void* d_out, int out_size) {
    const int*   tokens = (const int*)d_in[0];
    const float* casing = (const float*)d_in[1];
    const float* pos    = (const float*)d_in[2];
    const float* emb    = (const float*)d_in[3];
    const float* wi0    = (const float*)d_in[4];
    const float* bi0    = (const float*)d_in[5];
    const float* wh0    = (const float*)d_in[6];
    const float* bh0    = (const float*)d_in[7];
    const float* wi1    = (const float*)d_in[8];
    const float* bi1    = (const float*)d_in[9];
    const float* wh1    = (const float*)d_in[10];
    const float* bh1    = (const float*)d_in[11];
    const float* dec_w  = (const float*)d_in[12];
    const float* dec_b  = (const float*)d_in[13];
    const float* h_init = (const float*)d_in[14];   // [2, B, H]; layer0 slice at offset 0
    const float* c_init = (const float*)d_in[15];
    float* out = (float*)d_out;

    (void)in_sizes; (void)n_in; (void)out_size;

    // 1. Build padded input features (gather + concat)
    k_build_x<<<M_, 256>>>(tokens, casing, pos, emb);
    // 2. Pad wi0 to K=320
    k_pad_wi0<<<G4H, 256>>>(wi0);
    // 3. Precompute layer-0 i2h for ALL timesteps (time-parallel)
    k_gemm_pre0<<<dim3(G4H / G1_BN, M_ / G1_BM), 256>>>(bi0, bh0);
    // 4. Sequential layer-0 scan (only truly recurrent part)
    for (int t = 0; t < T_; t++)
        k_lstm0_step<<<dim3(H_ / L0_BN, B_ / L0_BM), 256>>>(t, h_init, c_init, wh0);
    // 5. Layer 1: stateless across time -> fully batch-parallel
    k_lstm1<<<dim3(H_ / L1_BN, M_ / L1_BM), 256>>>(wi1, wh1, bi1, bh1);
    // 6. Decode
    k_decode<<<(M_ * 32) / 256, 256>>>(dec_w, dec_b, out);
}

// round 2
// speedup vs baseline: 1.7895x; 1.7895x over previous
#include <cuda_runtime.h>

// Problem constants
#define T_    256
#define B_    256
#define H_    1024
#define E_    300
#define FEAT  319
#define FEATP 320
#define C_    13
#define G4H   4096
#define M_    (T_ * B_)

// -------- scratch (static device globals; no allocation anywhere) --------
__device__ float g_X[(size_t)M_ * FEATP];
__device__ float g_wi0p[(size_t)G4H * FEATP];
__device__ float g_pre0[(size_t)M_ * G4H];
__device__ float g_h0[(size_t)M_ * H_];
__device__ float g_c0[(size_t)M_ * H_];
__device__ float g_h1[(size_t)M_ * H_];

__device__ __forceinline__ float sigmoidf_(float x) {
    return 1.0f / (1.0f + __expf(-x));
}
__device__ __forceinline__ unsigned f2tf(float x) {
    unsigned u;
    asm("cvt.rna.tf32.f32 %0, %1;" : "=r"(u) : "f"(x));
    return u;
}
// D += A(16x8,row) * B(8x8,col) in tf32, fp32 accum
__device__ __forceinline__ void mma8(float* d, const unsigned* a, const unsigned* b) {
    asm volatile(
        "mma.sync.aligned.m16n8k8.row.col.f32.tf32.tf32.f32 "
        "{%0,%1,%2,%3}, {%4,%5,%6,%7}, {%8,%9}, {%0,%1,%2,%3};\n"
        : "+f"(d[0]), "+f"(d[1]), "+f"(d[2]), "+f"(d[3])
        : "r"(a[0]), "r"(a[1]), "r"(a[2]), "r"(a[3]), "r"(b[0]), "r"(b[1]));
}

// ===========================================================================
// Kernel 1: build X = [emb_table[tokens] | casing | pos | 0pad]
// ===========================================================================
__global__ void k_build_x(const int* __restrict__ tokens,
                          const float* __restrict__ casing,
                          const float* __restrict__ pos,
                          const float* __restrict__ emb) {
    int m = blockIdx.x;
    int tok = tokens[m];
    const float* erow = emb + (size_t)tok * E_;
    float* xrow = g_X + (size_t)m * FEATP;
    for (int k = threadIdx.x; k < FEATP; k += blockDim.x) {
        float v;
        if (k < E_)            v = erow[k];
        else if (k < E_ + 7)   v = casing[m * 7 + (k - E_)];
        else if (k < FEAT)     v = pos[m * 12 + (k - E_ - 7)];
        else                   v = 0.0f;
        xrow[k] = v;
    }
}

// ===========================================================================
// Kernel 2: pad wi0 [4096,319] -> [4096,320]
// ===========================================================================
__global__ void k_pad_wi0(const float* __restrict__ wi0) {
    int j = blockIdx.x;
    for (int k = threadIdx.x; k < FEATP; k += blockDim.x)
        g_wi0p[(size_t)j * FEATP + k] = (k < FEAT) ? wi0[(size_t)j * FEAT + k] : 0.0f;
}

// ===========================================================================
// Kernel 3 (tf32 mma): pre0 = X @ wi0p^T + (bi0+bh0)   [65536 x 4096], K=320
// BM=128, BN=128, BK=32; 8 warps (2 M x 4 N); warp tile 64x32.
// ===========================================================================
__global__ __launch_bounds__(256) void k_gemm_pre0(const float* __restrict__ bi0,
                                                   const float* __restrict__ bh0) {
    __shared__ unsigned As[32][136];   // [k][m], stride 136 = 8 (mod 32)
    __shared__ unsigned Bs[32][136];   // [k][n]

    const int m0 = blockIdx.y * 128;
    const int n0 = blockIdx.x * 128;
    const int tid = threadIdx.x, lane = tid & 31, wid = tid >> 5;
    const int wm = wid & 1, wn = wid >> 1;
    const int tg = lane & 3, gr = lane >> 2;

    float acc[4][4][4];
#pragma unroll
    for (int i = 0; i < 4; i++)
#pragma unroll
        for (int j = 0; j < 4; j++)
#pragma unroll
            for (int r = 0; r < 4; r++) acc[i][j][r] = 0.0f;

    float4 pa[4], pb[4];
    auto loadA = [&](int kc) {
#pragma unroll
        for (int it = 0; it < 4; it++) {
            int idx = tid + it * 256, mm = idx & 127, kq = idx >> 7;
            pa[it] = *(const float4*)(g_X + (size_t)(m0 + mm) * FEATP + kc * 32 + kq * 4);
        }
    };
    auto loadB = [&](int kc) {
#pragma unroll
        for (int it = 0; it < 4; it++) {
            int idx = tid + it * 256, nn = idx & 127, kq = idx >> 7;
            pb[it] = *(const float4*)(g_wi0p + (size_t)(n0 + nn) * FEATP + kc * 32 + kq * 4);
        }
    };
    auto stash = [&]() {
#pragma unroll
        for (int it = 0; it < 4; it++) {
            int idx = tid + it * 256, mm = idx & 127, kq = idx >> 7;
            As[kq * 4 + 0][mm] = f2tf(pa[it].x); As[kq * 4 + 1][mm] = f2tf(pa[it].y);
            As[kq * 4 + 2][mm] = f2tf(pa[it].z); As[kq * 4 + 3][mm] = f2tf(pa[it].w);
        }
#pragma unroll
        for (int it = 0; it < 4; it++) {
            int idx = tid + it * 256, nn = idx & 127, kq = idx >> 7;
            Bs[kq * 4 + 0][nn] = f2tf(pb[it].x); Bs[kq * 4 + 1][nn] = f2tf(pb[it].y);
            Bs[kq * 4 + 2][nn] = f2tf(pb[it].z); Bs[kq * 4 + 3][nn] = f2tf(pb[it].w);
        }
    };

    loadA(0); loadB(0);
    for (int kc = 0; kc < FEATP / 32; kc++) {
        __syncthreads();
        stash();
        __syncthreads();
        if (kc + 1 < FEATP / 32) { loadA(kc + 1); loadB(kc + 1); }
#pragma unroll
        for (int ks = 0; ks < 4; ks++) {
            const int k8 = ks * 8;
            unsigned a[4][4], b[4][2];
#pragma unroll
            for (int mt = 0; mt < 4; mt++) {
                int mb = wm * 64 + mt * 16;
                a[mt][0] = As[k8 + tg][mb + gr];
                a[mt][1] = As[k8 + tg][mb + 8 + gr];
                a[mt][2] = As[k8 + 4 + tg][mb + gr];
                a[mt][3] = As[k8 + 4 + tg][mb + 8 + gr];
            }
#pragma unroll
            for (int nt = 0; nt < 4; nt++) {
                int nb = wn * 32 + nt * 8;
                b[nt][0] = Bs[k8 + tg][nb + gr];
                b[nt][1] = Bs[k8 + 4 + tg][nb + gr];
            }
#pragma unroll
            for (int mt = 0; mt < 4; mt++)
#pragma unroll
                for (int nt = 0; nt < 4; nt++) mma8(acc[mt][nt], a[mt], b[nt]);
        }
    }

#pragma unroll
    for (int nt = 0; nt < 4; nt++) {
        int n = n0 + wn * 32 + nt * 8 + 2 * tg;
        float b0 = bi0[n] + bh0[n];
        float b1 = bi0[n + 1] + bh0[n + 1];
#pragma unroll
        for (int mt = 0; mt < 4; mt++) {
            int m = m0 + wm * 64 + mt * 16 + gr;
            float2 v0 = make_float2(acc[mt][nt][0] + b0, acc[mt][nt][1] + b1);
            float2 v1 = make_float2(acc[mt][nt][2] + b0, acc[mt][nt][3] + b1);
            *(float2*)(g_pre0 + (size_t)m * G4H + n) = v0;
            *(float2*)(g_pre0 + (size_t)(m + 8) * G4H + n) = v1;
        }
    }
}

// ===========================================================================
// Kernel 4 (tf32 mma): layer-0 LSTM step. Gate-fused h2h GEMM.
// BM=64 batch rows, 32 cols per gate (x4 gates). 8 warps: 2 M x 4 N.
// Warp: 32 rows x 8 cols per gate. Grid 32 x 4 = 128 CTAs.
// ===========================================================================
__global__ __launch_bounds__(256) void k_lstm0_step(int t,
                                                    const float* __restrict__ h_init0,
                                                    const float* __restrict__ c_init0,
                                                    const float* __restrict__ wh0) {
    __shared__ unsigned As[32][72];      // [k][m], 72 = 8 (mod 32)
    __shared__ unsigned Bs[4][32][40];   // per gate [k][n], 40 = 8 (mod 32)

    const float* hprev = (t == 0) ? h_init0 : (g_h0 + (size_t)(t - 1) * B_ * H_);
    const float* cprev = (t == 0) ? c_init0 : (g_c0 + (size_t)(t - 1) * B_ * H_);
    const float* pre0t = g_pre0 + (size_t)t * B_ * G4H;
    float* hout = g_h0 + (size_t)t * B_ * H_;
    float* cout = g_c0 + (size_t)t * B_ * H_;

    const int m0 = blockIdx.y * 64;
    const int n0 = blockIdx.x * 32;
    const int tid = threadIdx.x, lane = tid & 31, wid = tid >> 5;
    const int wm = wid & 1, wn = wid >> 1;
    const int tg = lane & 3, gr = lane >> 2;

    float acc[4][2][4];
#pragma unroll
    for (int g = 0; g < 4; g++)
#pragma unroll
        for (int mt = 0; mt < 2; mt++)
#pragma unroll
            for (int r = 0; r < 4; r++) acc[g][mt][r] = 0.0f;

    float4 pa[2], pb[4];
    auto loadA = [&](int kc) {
#pragma unroll
        for (int it = 0; it < 2; it++) {
            int idx = tid + it * 256, mm = idx & 63, kq = idx >> 6;
            pa[it] = *(const float4*)(hprev + (size_t)(m0 + mm) * H_ + kc * 32 + kq * 4);
        }
    };
    auto loadB = [&](int kc) {
#pragma unroll
        for (int it = 0; it < 4; it++) {
            int idx = tid + it * 256;
            int gsel = idx >> 8, nn = idx & 31, kq = (idx >> 5) & 7;
            pb[it] = *(const float4*)(wh0 + (size_t)(gsel * H_ + n0 + nn) * H_ + kc * 32 + kq * 4);
        }
    };
    auto stash = [&]() {
#pragma unroll
        for (int it = 0; it < 2; it++) {
            int idx = tid + it * 256, mm = idx & 63, kq = idx >> 6;
            As[kq * 4 + 0][mm] = f2tf(pa[it].x); As[kq * 4 + 1][mm] = f2tf(pa[it].y);
            As[kq * 4 + 2][mm] = f2tf(pa[it].z); As[kq * 4 + 3][mm] = f2tf(pa[it].w);
        }
#pragma unroll
        for (int it = 0; it < 4; it++) {
            int idx = tid + it * 256;
            int gsel = idx >> 8, nn = idx & 31, kq = (idx >> 5) & 7;
            Bs[gsel][kq * 4 + 0][nn] = f2tf(pb[it].x); Bs[gsel][kq * 4 + 1][nn] = f2tf(pb[it].y);
            Bs[gsel][kq * 4 + 2][nn] = f2tf(pb[it].z); Bs[gsel][kq * 4 + 3][nn] = f2tf(pb[it].w);
        }
    };

    loadA(0); loadB(0);
    for (int kc = 0; kc < H_ / 32; kc++) {
        __syncthreads();
        stash();
        __syncthreads();
        if (kc + 1 < H_ / 32) { loadA(kc + 1); loadB(kc + 1); }
#pragma unroll
        for (int ks = 0; ks < 4; ks++) {
            const int k8 = ks * 8;
            unsigned a[2][4];
#pragma unroll
            for (int mt = 0; mt < 2; mt++) {
                int mb = wm * 32 + mt * 16;
                a[mt][0] = As[k8 + tg][mb + gr];
                a[mt][1] = As[k8 + tg][mb + 8 + gr];
                a[mt][2] = As[k8 + 4 + tg][mb + gr];
                a[mt][3] = As[k8 + 4 + tg][mb + 8 + gr];
            }
#pragma unroll
            for (int g = 0; g < 4; g++) {
                unsigned b[2];
                b[0] = Bs[g][k8 + tg][wn * 8 + gr];
                b[1] = Bs[g][k8 + 4 + tg][wn * 8 + gr];
                mma8(acc[g][0], a[0], b);
                mma8(acc[g][1], a[1], b);
            }
        }
    }

    // fused gate epilogue
#pragma unroll
    for (int mt = 0; mt < 2; mt++)
#pragma unroll
        for (int half = 0; half < 2; half++) {
            int m = m0 + wm * 32 + mt * 16 + half * 8 + gr;
            const float* p = pre0t + (size_t)m * G4H;
            const float* cp = cprev + (size_t)m * H_;
            float* hp = hout + (size_t)m * H_;
            float* co = cout + (size_t)m * H_;
#pragma unroll
            for (int cc = 0; cc < 2; cc++) {
                int nn = n0 + wn * 8 + 2 * tg + cc;
                int r = half * 2 + cc;
                float pi = acc[0][mt][r] + p[nn];
                float pf = acc[1][mt][r] + p[H_ + nn];
                float po = acc[2][mt][r] + p[2 * H_ + nn];
                float pg = acc[3][mt][r] + p[3 * H_ + nn];
                float c = sigmoidf_(pf) * cp[nn] + sigmoidf_(pi) * tanhf(pg);
                hp[nn] = sigmoidf_(po) * tanhf(c);
                co[nn] = c;
            }
        }
}

// ===========================================================================
// Kernel 5 (tf32 mma): layer-1, batch-parallel (stateless across time).
// K=2048 (wi1 on h0[m], then wh1 on h0[mflip]). BM=128, 32 cols/gate.
// 8 warps: 4 M x 2 N; warp 32 rows x 16 cols per gate. Grid 32 x 512.
// ===========================================================================
__global__ __launch_bounds__(256) void k_lstm1(const float* __restrict__ wi1,
                                               const float* __restrict__ wh1,
                                               const float* __restrict__ bi1,
                                               const float* __restrict__ bh1) {
    __shared__ unsigned As[32][136];
    __shared__ unsigned Bs[4][32][40];

    const int m0 = blockIdx.y * 128;
    const int n0 = blockIdx.x * 32;
    const int tid = threadIdx.x, lane = tid & 31, wid = tid >> 5;
    const int wm = wid & 3, wn = wid >> 2;
    const int tg = lane & 3, gr = lane >> 2;

    float acc[4][2][2][4];
#pragma unroll
    for (int g = 0; g < 4; g++)
#pragma unroll
        for (int mt = 0; mt < 2; mt++)
#pragma unroll
            for (int nt = 0; nt < 2; nt++)
#pragma unroll
                for (int r = 0; r < 4; r++) acc[g][mt][nt][r] = 0.0f;

    float4 pa[4], pb[4];
    auto loadA = [&](int kc) {
        bool second = (kc >= 32);
        int kk0 = (kc * 32) & (H_ - 1);
#pragma unroll
        for (int it = 0; it < 4; it++) {
            int idx = tid + it * 256, mm = idx & 127, kq = idx >> 7;
            int m = m0 + mm, bq = m & 255;
            int msel = second ? (m - bq + 255 - bq) : m;
            pa[it] = *(const float4*)(g_h0 + (size_t)msel * H_ + kk0 + kq * 4);
        }
    };
    auto loadB = [&](int kc) {
        const float* W = (kc >= 32) ? wh1 : wi1;
        int kk0 = (kc * 32) & (H_ - 1);
#pragma unroll
        for (int it = 0; it < 4; it++) {
            int idx = tid + it * 256;
            int gsel = idx >> 8, nn = idx & 31, kq = (idx >> 5) & 7;
            pb[it] = *(const float4*)(W + (size_t)(gsel * H_ + n0 + nn) * H_ + kk0 + kq * 4);
        }
    };
    auto stash = [&]() {
#pragma unroll
        for (int it = 0; it < 4; it++) {
            int idx = tid + it * 256, mm = idx & 127, kq = idx >> 7;
            As[kq * 4 + 0][mm] = f2tf(pa[it].x); As[kq * 4 + 1][mm] = f2tf(pa[it].y);
            As[kq * 4 + 2][mm] = f2tf(pa[it].z); As[kq * 4 + 3][mm] = f2tf(pa[it].w);
        }
#pragma unroll
        for (int it = 0; it < 4; it++) {
            int idx = tid + it * 256;
            int gsel = idx >> 8, nn = idx & 31, kq = (idx >> 5) & 7;
            Bs[gsel][kq * 4 + 0][nn] = f2tf(pb[it].x); Bs[gsel][kq * 4 + 1][nn] = f2tf(pb[it].y);
            Bs[gsel][kq * 4 + 2][nn] = f2tf(pb[it].z); Bs[gsel][kq * 4 + 3][nn] = f2tf(pb[it].w);
        }
    };

    loadA(0); loadB(0);
    for (int kc = 0; kc < 64; kc++) {
        __syncthreads();
        stash();
        __syncthreads();
        if (kc + 1 < 64) { loadA(kc + 1); loadB(kc + 1); }
#pragma unroll
        for (int ks = 0; ks < 4; ks++) {
            const int k8 = ks * 8;
            unsigned a[2][4];
#pragma unroll
            for (int mt = 0; mt < 2; mt++) {
                int mb = wm * 32 + mt * 16;
                a[mt][0] = As[k8 + tg][mb + gr];
                a[mt][1] = As[k8 + tg][mb + 8 + gr];
                a[mt][2] = As[k8 + 4 + tg][mb + gr];
                a[mt][3] = As[k8 + 4 + tg][mb + 8 + gr];
            }
#pragma unroll
            for (int g = 0; g < 4; g++) {
#pragma unroll
                for (int nt = 0; nt < 2; nt++) {
                    unsigned b[2];
                    int nb = wn * 16 + nt * 8;
                    b[0] = Bs[g][k8 + tg][nb + gr];
                    b[1] = Bs[g][k8 + 4 + tg][nb + gr];
                    mma8(acc[g][0][nt], a[0], b);
                    mma8(acc[g][1][nt], a[1], b);
                }
            }
        }
    }

#pragma unroll
    for (int mt = 0; mt < 2; mt++)
#pragma unroll
        for (int half = 0; half < 2; half++) {
            int m = m0 + wm * 32 + mt * 16 + half * 8 + gr;
            int bq = m & 255;
            int mflip = m - bq + 255 - bq;
            const float* cp = g_c0 + (size_t)mflip * H_;
            float* hp = g_h1 + (size_t)m * H_;
#pragma unroll
            for (int nt = 0; nt < 2; nt++)
#pragma unroll
                for (int cc = 0; cc < 2; cc++) {
                    int nn = n0 + wn * 16 + nt * 8 + 2 * tg + cc;
                    int r = half * 2 + cc;
                    float pi = acc[0][mt][nt][r] + bi1[nn] + bh1[nn];
                    float pf = acc[1][mt][nt][r] + bi1[H_ + nn] + bh1[H_ + nn];
                    float po = acc[2][mt][nt][r] + bi1[2 * H_ + nn] + bh1[2 * H_ + nn];
                    float pg = acc[3][mt][nt][r] + bi1[3 * H_ + nn] + bh1[3 * H_ + nn];
                    float c = sigmoidf_(pf) * cp[nn] + sigmoidf_(pi) * tanhf(pg);
                    hp[nn] = sigmoidf_(po) * tanhf(c);
                }
        }
}

// ===========================================================================
// Kernel 6: decode. out[m, c] = [h0[m] | h1[m]] . dec_w[c] + dec_b[c]
// ===========================================================================
__global__ __launch_bounds__(256) void k_decode(const float* __restrict__ dec_w,
                                                const float* __restrict__ dec_b,
                                                float* __restrict__ out) {
    int gwarp = (blockIdx.x * blockDim.x + threadIdx.x) >> 5;
    int lane = threadIdx.x & 31;
    if (gwarp >= M_) return;
    const float* h0r = g_h0 + (size_t)gwarp * H_;
    const float* h1r = g_h1 + (size_t)gwarp * H_;

    float acc[C_];
#pragma unroll
    for (int c = 0; c < C_; c++) acc[c] = 0.0f;

    for (int k = lane * 4; k < H_; k += 128) {
        float4 v0 = *(const float4*)(h0r + k);
        float4 v1 = *(const float4*)(h1r + k);
#pragma unroll
        for (int c = 0; c < C_; c++) {
            const float* w = dec_w + (size_t)c * 2 * H_;
            float4 w0 = *(const float4*)(w + k);
            float4 w1 = *(const float4*)(w + H_ + k);
            acc[c] += v0.x * w0.x + v0.y * w0.y + v0.z * w0.z + v0.w * w0.w
                    + v1.x * w1.x + v1.y * w1.y + v1.z * w1.z + v1.w * w1.w;
        }
    }
#pragma unroll
    for (int c = 0; c < C_; c++) {
#pragma unroll
        for (int off = 16; off > 0; off >>= 1)
            acc[c] += __shfl_down_sync(0xFFFFFFFFu, acc[c], off);
    }
    if (lane == 0) {
#pragma unroll
        for (int c = 0; c < C_; c++)
            out[(size_t)gwarp * C_ + c] = acc[c] + dec_b[c];
    }
}

// ===========================================================================
// Launch
// ===========================================================================
extern "C" void kernel_launch(void* const* d_in, const int* in_sizes, int n_in,
                              void* d_out, int out_size) {
    const int*   tokens = (const int*)d_in[0];
    const float* casing = (const float*)d_in[1];
    const float* pos    = (const float*)d_in[2];
    const float* emb    = (const float*)d_in[3];
    const float* wi0    = (const float*)d_in[4];
    const float* bi0    = (const float*)d_in[5];
    const float* wh0    = (const float*)d_in[6];
    const float* bh0    = (const float*)d_in[7];
    const float* wi1    = (const float*)d_in[8];
    const float* bi1    = (const float*)d_in[9];
    const float* wh1    = (const float*)d_in[10];
    const float* bh1    = (const float*)d_in[11];
    const float* dec_w  = (const float*)d_in[12];
    const float* dec_b  = (const float*)d_in[13];
    const float* h_init = (const float*)d_in[14];
    const float* c_init = (const float*)d_in[15];
    float* out = (float*)d_out;

    (void)in_sizes; (void)n_in; (void)out_size;

    k_build_x<<<M_, 256>>>(tokens, casing, pos, emb);
    k_pad_wi0<<<G4H, 256>>>(wi0);
    k_gemm_pre0<<<dim3(G4H / 128, M_ / 128), 256>>>(bi0, bh0);
    for (int t = 0; t < T_; t++)
        k_lstm0_step<<<dim3(H_ / 32, B_ / 64), 256>>>(t, h_init, c_init, wh0);
    k_lstm1<<<dim3(H_ / 32, M_ / 128), 256>>>(wi1, wh1, bi1, bh1);
    k_decode<<<(M_ * 32) / 256, 256>>>(dec_w, dec_b, out);
}

// round 3
// speedup vs baseline: 2.1865x; 1.2218x over previous
#include <cuda_runtime.h>

// Problem constants
#define T_    256
#define B_    256
#define H_    1024
#define E_    300
#define FEAT  319
#define FEATP 320
#define C_    13
#define G4H   4096
#define M_    (T_ * B_)

#define SCAN_NCTA 128
// dynamic smem: Ws[4][1024][8] (131072 B) + Hs[2][256][36] (73728 B)
#define SCAN_SMEM (4 * 1024 * 8 * 4 + 2 * 256 * 36 * 4)

// -------- scratch (static device globals; no allocation anywhere) --------
__device__ float g_X[(size_t)M_ * FEATP];
__device__ float g_wi0p[(size_t)G4H * FEATP];
__device__ float g_pre0[(size_t)M_ * G4H];
__device__ float g_h0[(size_t)M_ * H_];
__device__ float g_c0[(size_t)M_ * H_];
__device__ float g_h1[(size_t)M_ * H_];
__device__ unsigned g_bar;

__device__ __forceinline__ float sigmoidf_(float x) {
    return 1.0f / (1.0f + __expf(-x));
}
__device__ __forceinline__ unsigned f2tf(float x) {
    unsigned u;
    asm("cvt.rna.tf32.f32 %0, %1;" : "=r"(u) : "f"(x));
    return u;
}
// D += A(16x8,row) * B(8x8,col) in tf32, fp32 accum
__device__ __forceinline__ void mma8(float* d, const unsigned* a, const unsigned* b) {
    asm volatile(
        "mma.sync.aligned.m16n8k8.row.col.f32.tf32.tf32.f32 "
        "{%0,%1,%2,%3}, {%4,%5,%6,%7}, {%8,%9}, {%0,%1,%2,%3};\n"
        : "+f"(d[0]), "+f"(d[1]), "+f"(d[2]), "+f"(d[3])
        : "r"(a[0]), "r"(a[1]), "r"(a[2]), "r"(a[3]), "r"(b[0]), "r"(b[1]));
}

__global__ void k_reset() { g_bar = 0u; }

// ===========================================================================
// Kernel 1: build X = [emb_table[tokens] | casing | pos | 0pad]
// ===========================================================================
__global__ void k_build_x(const int* __restrict__ tokens,
                          const float* __restrict__ casing,
                          const float* __restrict__ pos,
                          const float* __restrict__ emb) {
    int m = blockIdx.x;
    int tok = tokens[m];
    const float* erow = emb + (size_t)tok * E_;
    float* xrow = g_X + (size_t)m * FEATP;
    for (int k = threadIdx.x; k < FEATP; k += blockDim.x) {
        float v;
        if (k < E_)            v = erow[k];
        else if (k < E_ + 7)   v = casing[m * 7 + (k - E_)];
        else if (k < FEAT)     v = pos[m * 12 + (k - E_ - 7)];
        else                   v = 0.0f;
        xrow[k] = v;
    }
}

// ===========================================================================
// Kernel 2: pad wi0 [4096,319] -> [4096,320]
// ===========================================================================
__global__ void k_pad_wi0(const float* __restrict__ wi0) {
    int j = blockIdx.x;
    for (int k = threadIdx.x; k < FEATP; k += blockDim.x)
        g_wi0p[(size_t)j * FEATP + k] = (k < FEAT) ? wi0[(size_t)j * FEAT + k] : 0.0f;
}

// ===========================================================================
// Kernel 3 (tf32 mma): pre0 = X @ wi0p^T + (bi0+bh0)   [65536 x 4096], K=320
// ===========================================================================
__global__ __launch_bounds__(256) void k_gemm_pre0(const float* __restrict__ bi0,
                                                   const float* __restrict__ bh0) {
    __shared__ unsigned As[32][136];
    __shared__ unsigned Bs[32][136];

    const int m0 = blockIdx.y * 128;
    const int n0 = blockIdx.x * 128;
    const int tid = threadIdx.x, lane = tid & 31, wid = tid >> 5;
    const int wm = wid & 1, wn = wid >> 1;
    const int tg = lane & 3, gr = lane >> 2;

    float acc[4][4][4];
#pragma unroll
    for (int i = 0; i < 4; i++)
#pragma unroll
        for (int j = 0; j < 4; j++)
#pragma unroll
            for (int r = 0; r < 4; r++) acc[i][j][r] = 0.0f;

    float4 pa[4], pb[4];
    auto loadA = [&](int kc) {
#pragma unroll
        for (int it = 0; it < 4; it++) {
            int idx = tid + it * 256, mm = idx & 127, kq = idx >> 7;
            pa[it] = *(const float4*)(g_X + (size_t)(m0 + mm) * FEATP + kc * 32 + kq * 4);
        }
    };
    auto loadB = [&](int kc) {
#pragma unroll
        for (int it = 0; it < 4; it++) {
            int idx = tid + it * 256, nn = idx & 127, kq = idx >> 7;
            pb[it] = *(const float4*)(g_wi0p + (size_t)(n0 + nn) * FEATP + kc * 32 + kq * 4);
        }
    };
    auto stash = [&]() {
#pragma unroll
        for (int it = 0; it < 4; it++) {
            int idx = tid + it * 256, mm = idx & 127, kq = idx >> 7;
            As[kq * 4 + 0][mm] = f2tf(pa[it].x); As[kq * 4 + 1][mm] = f2tf(pa[it].y);
            As[kq * 4 + 2][mm] = f2tf(pa[it].z); As[kq * 4 + 3][mm] = f2tf(pa[it].w);
        }
#pragma unroll
        for (int it = 0; it < 4; it++) {
            int idx = tid + it * 256, nn = idx & 127, kq = idx >> 7;
            Bs[kq * 4 + 0][nn] = f2tf(pb[it].x); Bs[kq * 4 + 1][nn] = f2tf(pb[it].y);
            Bs[kq * 4 + 2][nn] = f2tf(pb[it].z); Bs[kq * 4 + 3][nn] = f2tf(pb[it].w);
        }
    };

    loadA(0); loadB(0);
    for (int kc = 0; kc < FEATP / 32; kc++) {
        __syncthreads();
        stash();
        __syncthreads();
        if (kc + 1 < FEATP / 32) { loadA(kc + 1); loadB(kc + 1); }
#pragma unroll
        for (int ks = 0; ks < 4; ks++) {
            const int k8 = ks * 8;
            unsigned a[4][4], b[4][2];
#pragma unroll
            for (int mt = 0; mt < 4; mt++) {
                int mb = wm * 64 + mt * 16;
                a[mt][0] = As[k8 + tg][mb + gr];
                a[mt][1] = As[k8 + tg][mb + 8 + gr];
                a[mt][2] = As[k8 + 4 + tg][mb + gr];
                a[mt][3] = As[k8 + 4 + tg][mb + 8 + gr];
            }
#pragma unroll
            for (int nt = 0; nt < 4; nt++) {
                int nb = wn * 32 + nt * 8;
                b[nt][0] = Bs[k8 + tg][nb + gr];
                b[nt][1] = Bs[k8 + 4 + tg][nb + gr];
            }
#pragma unroll
            for (int mt = 0; mt < 4; mt++)
#pragma unroll
                for (int nt = 0; nt < 4; nt++) mma8(acc[mt][nt], a[mt], b[nt]);
        }
    }

#pragma unroll
    for (int nt = 0; nt < 4; nt++) {
        int n = n0 + wn * 32 + nt * 8 + 2 * tg;
        float b0 = bi0[n] + bh0[n];
        float b1 = bi0[n + 1] + bh0[n + 1];
#pragma unroll
        for (int mt = 0; mt < 4; mt++) {
            int m = m0 + wm * 64 + mt * 16 + gr;
            float2 v0 = make_float2(acc[mt][nt][0] + b0, acc[mt][nt][1] + b1);
            float2 v1 = make_float2(acc[mt][nt][2] + b0, acc[mt][nt][3] + b1);
            *(float2*)(g_pre0 + (size_t)m * G4H + n) = v0;
            *(float2*)(g_pre0 + (size_t)(m + 8) * G4H + n) = v1;
        }
    }
}

// ===========================================================================
// Kernel 4: PERSISTENT layer-0 scan. 128 CTAs, one per SM region; CTA nb owns
// cols [nb*8, nb*8+8) in each of the 4 gates. wh0 slab lives in SMEM (tf32)
// for all 256 steps. h_prev streamed via ping-pong SMEM, 1 sync per chunk.
// c state lives in registers. Inter-CTA sync = monotonic atomic barrier.
// ===========================================================================
__global__ __launch_bounds__(256, 1) void k_lstm0_scan(
    const float* __restrict__ h_init0, const float* __restrict__ c_init0,
    const float* __restrict__ wh0) {
    extern __shared__ unsigned smx[];
    unsigned* Ws = smx;                     // [4][1024][8]  (g*8192 + k*8 + n)
    unsigned* Hs = smx + 4 * 1024 * 8;      // [2][256][36]  (buf*9216 + m*36 + k)

    const int tid = threadIdx.x, lane = tid & 31, wid = tid >> 5;
    const int tg = lane & 3, gr = lane >> 2;
    const int n0 = blockIdx.x * 8;
    const int mb = wid * 32;
    const int mrow = tid >> 3, kq = tid & 7;   // staging coords

    // ---- one-time: weight slab -> SMEM as tf32 ----
#pragma unroll
    for (int rr = 0; rr < 4; rr++) {
        int r = wid * 4 + rr;               // 0..31 = g*8 + n
        int g = r >> 3, n = r & 7;
        const float* src = wh0 + (size_t)(g * H_ + n0 + n) * H_;
        unsigned* dst = Ws + g * 8192 + n;
        for (int k4 = lane; k4 < 256; k4 += 32) {
            float4 v = *(const float4*)(src + k4 * 4);
            dst[(k4 * 4 + 0) * 8] = f2tf(v.x);
            dst[(k4 * 4 + 1) * 8] = f2tf(v.y);
            dst[(k4 * 4 + 2) * 8] = f2tf(v.z);
            dst[(k4 * 4 + 3) * 8] = f2tf(v.w);
        }
    }

    // ---- c state in registers (thread's output coords are step-invariant) ----
    float creg[2][2][2];
#pragma unroll
    for (int mt = 0; mt < 2; mt++)
#pragma unroll
        for (int hf = 0; hf < 2; hf++) {
            int m = mb + mt * 16 + hf * 8 + gr;
            float2 cv = *(const float2*)(c_init0 + (size_t)m * H_ + n0 + 2 * tg);
            creg[mt][hf][0] = cv.x;
            creg[mt][hf][1] = cv.y;
        }

    float acc[4][2][4];
#pragma unroll
    for (int g = 0; g < 4; g++)
#pragma unroll
        for (int mt = 0; mt < 2; mt++)
#pragma unroll
            for (int r = 0; r < 4; r++) acc[g][mt][r] = 0.0f;

    __syncthreads();   // weights visible

    for (int t = 0; t < T_; t++) {
        const float* hprev = (t == 0) ? h_init0 : (g_h0 + (size_t)(t - 1) * B_ * H_);
        float* hout = g_h0 + (size_t)t * B_ * H_;
        float* cout = g_c0 + (size_t)t * B_ * H_;
        const float* pt = g_pre0 + (size_t)t * B_ * G4H;

        float4 pf[8];
        // prefetch + stash chunk 0
#pragma unroll
        for (int i = 0; i < 8; i++)
            pf[i] = *(const float4*)(hprev + (size_t)(mrow + 32 * i) * H_ + kq * 4);
        {
            unsigned* base = Hs;
#pragma unroll
            for (int i = 0; i < 8; i++) {
                uint4 u;
                u.x = f2tf(pf[i].x); u.y = f2tf(pf[i].y);
                u.z = f2tf(pf[i].z); u.w = f2tf(pf[i].w);
                *(uint4*)(base + (mrow + 32 * i) * 36 + kq * 4) = u;
            }
        }
        __syncthreads();

        for (int kc = 0; kc < 32; kc++) {
            if (kc + 1 < 32) {
#pragma unroll
                for (int i = 0; i < 8; i++)
                    pf[i] = *(const float4*)(hprev + (size_t)(mrow + 32 * i) * H_ +
                                             (kc + 1) * 32 + kq * 4);
            }
            const unsigned* Hb = Hs + (kc & 1) * 9216;
            const int kbase = kc * 32;
#pragma unroll
            for (int ks = 0; ks < 4; ks++) {
                const int k8 = ks * 8;
                unsigned a[2][4];
#pragma unroll
                for (int mt = 0; mt < 2; mt++) {
                    const unsigned* r0 = Hb + (mb + mt * 16 + gr) * 36;
                    const unsigned* r1 = r0 + 8 * 36;
                    a[mt][0] = r0[k8 + tg];
                    a[mt][1] = r1[k8 + tg];
                    a[mt][2] = r0[k8 + 4 + tg];
                    a[mt][3] = r1[k8 + 4 + tg];
                }
#pragma unroll
                for (int g = 0; g < 4; g++) {
                    const unsigned* wg = Ws + g * 8192 + (kbase + k8) * 8;
                    unsigned bb[2];
                    bb[0] = wg[tg * 8 + gr];
                    bb[1] = wg[(4 + tg) * 8 + gr];
                    mma8(acc[g][0], a[0], bb);
                    mma8(acc[g][1], a[1], bb);
                }
            }
            if (kc + 1 < 32) {
                unsigned* base = Hs + ((kc + 1) & 1) * 9216;
#pragma unroll
                for (int i = 0; i < 8; i++) {
                    uint4 u;
                    u.x = f2tf(pf[i].x); u.y = f2tf(pf[i].y);
                    u.z = f2tf(pf[i].z); u.w = f2tf(pf[i].w);
                    *(uint4*)(base + (mrow + 32 * i) * 36 + kq * 4) = u;
                }
            }
            __syncthreads();
        }

        // ---- fused gate epilogue; c stays in registers ----
#pragma unroll
        for (int mt = 0; mt < 2; mt++)
#pragma unroll
            for (int hf = 0; hf < 2; hf++) {
                int m = mb + mt * 16 + hf * 8 + gr;
                const float* p = pt + (size_t)m * G4H + n0 + 2 * tg;
                float2 Pi = *(const float2*)(p);
                float2 Pf = *(const float2*)(p + H_);
                float2 Po = *(const float2*)(p + 2 * H_);
                float2 Pg = *(const float2*)(p + 3 * H_);
                float h2[2];
#pragma unroll
                for (int cc = 0; cc < 2; cc++) {
                    int r = hf * 2 + cc;
                    float pi = acc[0][mt][r] + (cc ? Pi.y : Pi.x);
                    float pfv = acc[1][mt][r] + (cc ? Pf.y : Pf.x);
                    float po = acc[2][mt][r] + (cc ? Po.y : Po.x);
                    float pg = acc[3][mt][r] + (cc ? Pg.y : Pg.x);
                    float c = sigmoidf_(pfv) * creg[mt][hf][cc] + sigmoidf_(pi) * tanhf(pg);
                    creg[mt][hf][cc] = c;
                    h2[cc] = sigmoidf_(po) * tanhf(c);
                }
                *(float2*)(hout + (size_t)m * H_ + n0 + 2 * tg) = make_float2(h2[0], h2[1]);
                *(float2*)(cout + (size_t)m * H_ + n0 + 2 * tg) =
                    make_float2(creg[mt][hf][0], creg[mt][hf][1]);
            }
#pragma unroll
        for (int g = 0; g < 4; g++)
#pragma unroll
            for (int mt = 0; mt < 2; mt++)
#pragma unroll
                for (int r = 0; r < 4; r++) acc[g][mt][r] = 0.0f;

        // ---- inter-CTA barrier (monotonic counter; reset by k_reset) ----
        __syncthreads();
        if (tid == 0) {
            __threadfence();
            atomicAdd(&g_bar, 1u);
            unsigned tgt = (unsigned)(t + 1) * SCAN_NCTA;
            while (atomicAdd(&g_bar, 0u) < tgt) __nanosleep(64);
            __threadfence();
        }
        __syncthreads();
    }
}

// ===========================================================================
// Kernel 5 (tf32 mma): layer-1, batch-parallel (stateless across time).
// ===========================================================================
__global__ __launch_bounds__(256) void k_lstm1(const float* __restrict__ wi1,
                                               const float* __restrict__ wh1,
                                               const float* __restrict__ bi1,
                                               const float* __restrict__ bh1) {
    __shared__ unsigned As[32][136];
    __shared__ unsigned Bs[4][32][40];

    const int m0 = blockIdx.y * 128;
    const int n0 = blockIdx.x * 32;
    const int tid = threadIdx.x, lane = tid & 31, wid = tid >> 5;
    const int wm = wid & 3, wn = wid >> 2;
    const int tg = lane & 3, gr = lane >> 2;

    float acc[4][2][2][4];
#pragma unroll
    for (int g = 0; g < 4; g++)
#pragma unroll
        for (int mt = 0; mt < 2; mt++)
#pragma unroll
            for (int nt = 0; nt < 2; nt++)
#pragma unroll
                for (int r = 0; r < 4; r++) acc[g][mt][nt][r] = 0.0f;

    float4 pa[4], pb[4];
    auto loadA = [&](int kc) {
        bool second = (kc >= 32);
        int kk0 = (kc * 32) & (H_ - 1);
#pragma unroll
        for (int it = 0; it < 4; it++) {
            int idx = tid + it * 256, mm = idx & 127, kq = idx >> 7;
            int m = m0 + mm, bq = m & 255;
            int msel = second ? (m - bq + 255 - bq) : m;
            pa[it] = *(const float4*)(g_h0 + (size_t)msel * H_ + kk0 + kq * 4);
        }
    };
    auto loadB = [&](int kc) {
        const float* W = (kc >= 32) ? wh1 : wi1;
        int kk0 = (kc * 32) & (H_ - 1);
#pragma unroll
        for (int it = 0; it < 4; it++) {
            int idx = tid + it * 256;
            int gsel = idx >> 8, nn = idx & 31, kq = (idx >> 5) & 7;
            pb[it] = *(const float4*)(W + (size_t)(gsel * H_ + n0 + nn) * H_ + kk0 + kq * 4);
        }
    };
    auto stash = [&]() {
#pragma unroll
        for (int it = 0; it < 4; it++) {
            int idx = tid + it * 256, mm = idx & 127, kq = idx >> 7;
            As[kq * 4 + 0][mm] = f2tf(pa[it].x); As[kq * 4 + 1][mm] = f2tf(pa[it].y);
            As[kq * 4 + 2][mm] = f2tf(pa[it].z); As[kq * 4 + 3][mm] = f2tf(pa[it].w);
        }
#pragma unroll
        for (int it = 0; it < 4; it++) {
            int idx = tid + it * 256;
            int gsel = idx >> 8, nn = idx & 31, kq = (idx >> 5) & 7;
            Bs[gsel][kq * 4 + 0][nn] = f2tf(pb[it].x); Bs[gsel][kq * 4 + 1][nn] = f2tf(pb[it].y);
            Bs[gsel][kq * 4 + 2][nn] = f2tf(pb[it].z); Bs[gsel][kq * 4 + 3][nn] = f2tf(pb[it].w);
        }
    };

    loadA(0); loadB(0);
    for (int kc = 0; kc < 64; kc++) {
        __syncthreads();
        stash();
        __syncthreads();
        if (kc + 1 < 64) { loadA(kc + 1); loadB(kc + 1); }
#pragma unroll
        for (int ks = 0; ks < 4; ks++) {
            const int k8 = ks * 8;
            unsigned a[2][4];
#pragma unroll
            for (int mt = 0; mt < 2; mt++) {
                int mbv = wm * 32 + mt * 16;
                a[mt][0] = As[k8 + tg][mbv + gr];
                a[mt][1] = As[k8 + tg][mbv + 8 + gr];
                a[mt][2] = As[k8 + 4 + tg][mbv + gr];
                a[mt][3] = As[k8 + 4 + tg][mbv + 8 + gr];
            }
#pragma unroll
            for (int g = 0; g < 4; g++) {
#pragma unroll
                for (int nt = 0; nt < 2; nt++) {
                    unsigned b[2];
                    int nb = wn * 16 + nt * 8;
                    b[0] = Bs[g][k8 + tg][nb + gr];
                    b[1] = Bs[g][k8 + 4 + tg][nb + gr];
                    mma8(acc[g][0][nt], a[0], b);
                    mma8(acc[g][1][nt], a[1], b);
                }
            }
        }
    }

#pragma unroll
    for (int mt = 0; mt < 2; mt++)
#pragma unroll
        for (int half = 0; half < 2; half++) {
            int m = m0 + wm * 32 + mt * 16 + half * 8 + gr;
            int bq = m & 255;
            int mflip = m - bq + 255 - bq;
            const float* cp = g_c0 + (size_t)mflip * H_;
            float* hp = g_h1 + (size_t)m * H_;
#pragma unroll
            for (int nt = 0; nt < 2; nt++)
#pragma unroll
                for (int cc = 0; cc < 2; cc++) {
                    int nn = n0 + wn * 16 + nt * 8 + 2 * tg + cc;
                    int r = half * 2 + cc;
                    float pi = acc[0][mt][nt][r] + bi1[nn] + bh1[nn];
                    float pf = acc[1][mt][nt][r] + bi1[H_ + nn] + bh1[H_ + nn];
                    float po = acc[2][mt][nt][r] + bi1[2 * H_ + nn] + bh1[2 * H_ + nn];
                    float pg = acc[3][mt][nt][r] + bi1[3 * H_ + nn] + bh1[3 * H_ + nn];
                    float c = sigmoidf_(pf) * cp[nn] + sigmoidf_(pi) * tanhf(pg);
                    hp[nn] = sigmoidf_(po) * tanhf(c);
                }
        }
}

// ===========================================================================
// Kernel 6: decode. out[m, c] = [h0[m] | h1[m]] . dec_w[c] + dec_b[c]
// ===========================================================================
__global__ __launch_bounds__(256) void k_decode(const float* __restrict__ dec_w,
                                                const float* __restrict__ dec_b,
                                                float* __restrict__ out) {
    int gwarp = (blockIdx.x * blockDim.x + threadIdx.x) >> 5;
    int lane = threadIdx.x & 31;
    if (gwarp >= M_) return;
    const float* h0r = g_h0 + (size_t)gwarp * H_;
    const float* h1r = g_h1 + (size_t)gwarp * H_;

    float acc[C_];
#pragma unroll
    for (int c = 0; c < C_; c++) acc[c] = 0.0f;

    for (int k = lane * 4; k < H_; k += 128) {
        float4 v0 = *(const float4*)(h0r + k);
        float4 v1 = *(const float4*)(h1r + k);
#pragma unroll
        for (int c = 0; c < C_; c++) {
            const float* w = dec_w + (size_t)c * 2 * H_;
            float4 w0 = *(const float4*)(w + k);
            float4 w1 = *(const float4*)(w + H_ + k);
            acc[c] += v0.x * w0.x + v0.y * w0.y + v0.z * w0.z + v0.w * w0.w
                    + v1.x * w1.x + v1.y * w1.y + v1.z * w1.z + v1.w * w1.w;
        }
    }
#pragma unroll
    for (int c = 0; c < C_; c++) {
#pragma unroll
        for (int off = 16; off > 0; off >>= 1)
            acc[c] += __shfl_down_sync(0xFFFFFFFFu, acc[c], off);
    }
    if (lane == 0) {
#pragma unroll
        for (int c = 0; c < C_; c++)
            out[(size_t)gwarp * C_ + c] = acc[c] + dec_b[c];
    }
}

// ===========================================================================
// Launch
// ===========================================================================
extern "C" void kernel_launch(void* const* d_in, const int* in_sizes, int n_in,
                              void* d_out, int out_size) {
    const int*   tokens = (const int*)d_in[0];
    const float* casing = (const float*)d_in[1];
    const float* pos    = (const float*)d_in[2];
    const float* emb    = (const float*)d_in[3];
    const float* wi0    = (const float*)d_in[4];
    const float* bi0    = (const float*)d_in[5];
    const float* wh0    = (const float*)d_in[6];
    const float* bh0    = (const float*)d_in[7];
    const float* wi1    = (const float*)d_in[8];
    const float* bi1    = (const float*)d_in[9];
    const float* wh1    = (const float*)d_in[10];
    const float* bh1    = (const float*)d_in[11];
    const float* dec_w  = (const float*)d_in[12];
    const float* dec_b  = (const float*)d_in[13];
    const float* h_init = (const float*)d_in[14];
    const float* c_init = (const float*)d_in[15];
    float* out = (float*)d_out;

    (void)in_sizes; (void)n_in; (void)out_size;

    cudaFuncSetAttribute(k_lstm0_scan, cudaFuncAttributeMaxDynamicSharedMemorySize,
                         SCAN_SMEM);

    k_reset<<<1, 1>>>();
    k_build_x<<<M_, 256>>>(tokens, casing, pos, emb);
    k_pad_wi0<<<G4H, 256>>>(wi0);
    k_gemm_pre0<<<dim3(G4H / 128, M_ / 128), 256>>>(bi0, bh0);
    k_lstm0_scan<<<SCAN_NCTA, 256, SCAN_SMEM>>>(h_init, c_init, wh0);
    k_lstm1<<<dim3(H_ / 32, M_ / 128), 256>>>(wi1, wh1, bi1, bh1);
    k_decode<<<(M_ * 32) / 256, 256>>>(dec_w, dec_b, out);
}

// round 4
// speedup vs baseline: 3.2534x; 1.4880x over previous
#include <cuda_runtime.h>

// Problem constants
#define T_    256
#define B_    256
#define H_    1024
#define E_    300
#define FEAT  319
#define FEATP 320
#define C_    13
#define G4H   4096
#define M_    (T_ * B_)

#define SCAN_NCTA 128
// Ws[4][1024][8] fp32 (131072 B) + Hs[4][256][20] fp32 (81920 B)
#define SCAN_SMEM (131072 + 81920)
// lstm1: 3 stages x (As[128][36] + Bs[4][32][36]) fp32
#define L1_SMEM (3 * (128 * 36 + 4 * 32 * 36) * 4)

// -------- scratch (static device globals; no allocation anywhere) --------
__device__ float g_X[(size_t)M_ * FEATP];
__device__ float g_wi0p[(size_t)G4H * FEATP];
__device__ float g_pre0[(size_t)M_ * G4H];
__device__ float g_h0[(size_t)M_ * H_];
__device__ float g_c0[(size_t)M_ * H_];
__device__ float g_h1[(size_t)M_ * H_];
__device__ unsigned g_bar;

__device__ __forceinline__ float sigmoidf_(float x) {
    return 1.0f / (1.0f + __expf(-x));
}
// D += A(16x8,row) * B(8x8,col); fp32 bits fed to tf32 MMA (HW truncates mantissa)
__device__ __forceinline__ void mma8(float* d, const unsigned* a, const unsigned* b) {
    asm volatile(
        "mma.sync.aligned.m16n8k8.row.col.f32.tf32.tf32.f32 "
        "{%0,%1,%2,%3}, {%4,%5,%6,%7}, {%8,%9}, {%0,%1,%2,%3};\n"
        : "+f"(d[0]), "+f"(d[1]), "+f"(d[2]), "+f"(d[3])
        : "r"(a[0]), "r"(a[1]), "r"(a[2]), "r"(a[3]), "r"(b[0]), "r"(b[1]));
}
__device__ __forceinline__ void cpa16(void* sdst, const void* gsrc) {
    unsigned s = (unsigned)__cvta_generic_to_shared(sdst);
    asm volatile("cp.async.cg.shared.global [%0], [%1], 16;\n" :: "r"(s), "l"(gsrc));
}
#define CP_COMMIT() asm volatile("cp.async.commit_group;\n" ::: "memory")
template <int N> __device__ __forceinline__ void cp_wait() {
    asm volatile("cp.async.wait_group %0;\n" :: "n"(N) : "memory");
}

__global__ void k_reset() { g_bar = 0u; }

// ===========================================================================
// Kernel 1: build X = [emb_table[tokens] | casing | pos | 0pad]
// ===========================================================================
__global__ void k_build_x(const int* __restrict__ tokens,
                          const float* __restrict__ casing,
                          const float* __restrict__ pos,
                          const float* __restrict__ emb) {
    int m = blockIdx.x;
    int tok = tokens[m];
    const float* erow = emb + (size_t)tok * E_;
    float* xrow = g_X + (size_t)m * FEATP;
    for (int k = threadIdx.x; k < FEATP; k += blockDim.x) {
        float v;
        if (k < E_)            v = erow[k];
        else if (k < E_ + 7)   v = casing[m * 7 + (k - E_)];
        else if (k < FEAT)     v = pos[m * 12 + (k - E_ - 7)];
        else                   v = 0.0f;
        xrow[k] = v;
    }
}

// ===========================================================================
// Kernel 2: pad wi0 [4096,319] -> [4096,320]
// ===========================================================================
__global__ void k_pad_wi0(const float* __restrict__ wi0) {
    int j = blockIdx.x;
    for (int k = threadIdx.x; k < FEATP; k += blockDim.x)
        g_wi0p[(size_t)j * FEATP + k] = (k < FEAT) ? wi0[(size_t)j * FEAT + k] : 0.0f;
}

// ===========================================================================
// Kernel 3: pre0 = X @ wi0p^T + (bi0+bh0)   [65536 x 4096], K=320
// ===========================================================================
__global__ __launch_bounds__(256) void k_gemm_pre0(const float* __restrict__ bi0,
                                                   const float* __restrict__ bh0) {
    __shared__ unsigned As[32][136];
    __shared__ unsigned Bs[32][136];

    const int m0 = blockIdx.y * 128;
    const int n0 = blockIdx.x * 128;
    const int tid = threadIdx.x, lane = tid & 31, wid = tid >> 5;
    const int wm = wid & 1, wn = wid >> 1;
    const int tg = lane & 3, gr = lane >> 2;

    float acc[4][4][4];
#pragma unroll
    for (int i = 0; i < 4; i++)
#pragma unroll
        for (int j = 0; j < 4; j++)
#pragma unroll
            for (int r = 0; r < 4; r++) acc[i][j][r] = 0.0f;

    float4 pa[4], pb[4];
    auto loadA = [&](int kc) {
#pragma unroll
        for (int it = 0; it < 4; it++) {
            int idx = tid + it * 256, mm = idx & 127, kq = idx >> 7;
            pa[it] = *(const float4*)(g_X + (size_t)(m0 + mm) * FEATP + kc * 32 + kq * 4);
        }
    };
    auto loadB = [&](int kc) {
#pragma unroll
        for (int it = 0; it < 4; it++) {
            int idx = tid + it * 256, nn = idx & 127, kq = idx >> 7;
            pb[it] = *(const float4*)(g_wi0p + (size_t)(n0 + nn) * FEATP + kc * 32 + kq * 4);
        }
    };
    auto stash = [&]() {
#pragma unroll
        for (int it = 0; it < 4; it++) {
            int idx = tid + it * 256, mm = idx & 127, kq = idx >> 7;
            As[kq * 4 + 0][mm] = __float_as_uint(pa[it].x);
            As[kq * 4 + 1][mm] = __float_as_uint(pa[it].y);
            As[kq * 4 + 2][mm] = __float_as_uint(pa[it].z);
            As[kq * 4 + 3][mm] = __float_as_uint(pa[it].w);
        }
#pragma unroll
        for (int it = 0; it < 4; it++) {
            int idx = tid + it * 256, nn = idx & 127, kq = idx >> 7;
            Bs[kq * 4 + 0][nn] = __float_as_uint(pb[it].x);
            Bs[kq * 4 + 1][nn] = __float_as_uint(pb[it].y);
            Bs[kq * 4 + 2][nn] = __float_as_uint(pb[it].z);
            Bs[kq * 4 + 3][nn] = __float_as_uint(pb[it].w);
        }
    };

    loadA(0); loadB(0);
    for (int kc = 0; kc < FEATP / 32; kc++) {
        __syncthreads();
        stash();
        __syncthreads();
        if (kc + 1 < FEATP / 32) { loadA(kc + 1); loadB(kc + 1); }
#pragma unroll
        for (int ks = 0; ks < 4; ks++) {
            const int k8 = ks * 8;
            unsigned a[4][4], b[4][2];
#pragma unroll
            for (int mt = 0; mt < 4; mt++) {
                int mb = wm * 64 + mt * 16;
                a[mt][0] = As[k8 + tg][mb + gr];
                a[mt][1] = As[k8 + tg][mb + 8 + gr];
                a[mt][2] = As[k8 + 4 + tg][mb + gr];
                a[mt][3] = As[k8 + 4 + tg][mb + 8 + gr];
            }
#pragma unroll
            for (int nt = 0; nt < 4; nt++) {
                int nb = wn * 32 + nt * 8;
                b[nt][0] = Bs[k8 + tg][nb + gr];
                b[nt][1] = Bs[k8 + 4 + tg][nb + gr];
            }
#pragma unroll
            for (int mt = 0; mt < 4; mt++)
#pragma unroll
                for (int nt = 0; nt < 4; nt++) mma8(acc[mt][nt], a[mt], b[nt]);
        }
    }

#pragma unroll
    for (int nt = 0; nt < 4; nt++) {
        int n = n0 + wn * 32 + nt * 8 + 2 * tg;
        float b0 = bi0[n] + bh0[n];
        float b1 = bi0[n + 1] + bh0[n + 1];
#pragma unroll
        for (int mt = 0; mt < 4; mt++) {
            int m = m0 + wm * 64 + mt * 16 + gr;
            float2 v0 = make_float2(acc[mt][nt][0] + b0, acc[mt][nt][1] + b1);
            float2 v1 = make_float2(acc[mt][nt][2] + b0, acc[mt][nt][3] + b1);
            *(float2*)(g_pre0 + (size_t)m * G4H + n) = v0;
            *(float2*)(g_pre0 + (size_t)(m + 8) * G4H + n) = v1;
        }
    }
}

// ===========================================================================
// Kernel 4: PERSISTENT layer-0 scan; 4-stage cp.async pipeline (k=16 chunks).
// CTA nb owns cols [nb*8, nb*8+8) per gate; wh0 slab SMEM-resident all steps.
// ===========================================================================
__global__ __launch_bounds__(256, 1) void k_lstm0_scan(
    const float* __restrict__ h_init0, const float* __restrict__ c_init0,
    const float* __restrict__ wh0) {
    extern __shared__ float smx[];
    float* Ws = smx;                     // [4][1024][8]  g*8192 + k*8 + n
    float* Hs = smx + 4 * 1024 * 8;      // [4][256][20]  stage*5120 + m*20 + k

    const int tid = threadIdx.x, lane = tid & 31, wid = tid >> 5;
    const int tg = lane & 3, gr = lane >> 2;
    const int n0 = blockIdx.x * 8;
    const int mb = wid * 32;

    // ---- one-time: weight slab -> SMEM ----
#pragma unroll
    for (int rr = 0; rr < 4; rr++) {
        int r = wid * 4 + rr;                // 0..31 = g*8 + n
        int g = r >> 3, n = r & 7;
        const float* src = wh0 + (size_t)(g * H_ + n0 + n) * H_;
        float* dst = Ws + g * 8192 + n;
        for (int k4 = lane; k4 < 256; k4 += 32) {
            float4 v = *(const float4*)(src + k4 * 4);
            dst[(k4 * 4 + 0) * 8] = v.x;
            dst[(k4 * 4 + 1) * 8] = v.y;
            dst[(k4 * 4 + 2) * 8] = v.z;
            dst[(k4 * 4 + 3) * 8] = v.w;
        }
    }

    // ---- c state in registers ----
    float creg[2][2][2];
#pragma unroll
    for (int mt = 0; mt < 2; mt++)
#pragma unroll
        for (int hf = 0; hf < 2; hf++) {
            int m = mb + mt * 16 + hf * 8 + gr;
            float2 cv = *(const float2*)(c_init0 + (size_t)m * H_ + n0 + 2 * tg);
            creg[mt][hf][0] = cv.x;
            creg[mt][hf][1] = cv.y;
        }

    float acc[4][2][4];
#pragma unroll
    for (int g = 0; g < 4; g++)
#pragma unroll
        for (int mt = 0; mt < 2; mt++)
#pragma unroll
            for (int r = 0; r < 4; r++) acc[g][mt][r] = 0.0f;

    __syncthreads();   // weights visible

    const int row_f = tid >> 2, q_f = tid & 3;   // fill coords (4 rows covered per it)

    for (int t = 0; t < T_; t++) {
        const float* hprev = (t == 0) ? h_init0 : (g_h0 + (size_t)(t - 1) * B_ * H_);
        float* hout = g_h0 + (size_t)t * B_ * H_;
        float* cout = g_c0 + (size_t)t * B_ * H_;
        const float* pt = g_pre0 + (size_t)t * B_ * G4H;

        auto fill = [&](int kc) {
            float* dst = Hs + (kc & 3) * 5120;
#pragma unroll
            for (int it = 0; it < 4; it++) {
                int row = row_f + it * 64;
                cpa16(dst + row * 20 + q_f * 4,
                      hprev + (size_t)row * H_ + kc * 16 + q_f * 4);
            }
        };

        fill(0); CP_COMMIT();
        fill(1); CP_COMMIT();
        fill(2); CP_COMMIT();

        for (int kc = 0; kc < 64; kc++) {
            cp_wait<2>();
            __syncthreads();
            const float* Hb = Hs + (kc & 3) * 5120;
#pragma unroll
            for (int ks = 0; ks < 2; ks++) {
                const int k8 = ks * 8;
                unsigned a[2][4];
#pragma unroll
                for (int mt = 0; mt < 2; mt++) {
                    const float* r0 = Hb + (mb + mt * 16 + gr) * 20;
                    const float* r1 = r0 + 8 * 20;
                    a[mt][0] = __float_as_uint(r0[k8 + tg]);
                    a[mt][1] = __float_as_uint(r1[k8 + tg]);
                    a[mt][2] = __float_as_uint(r0[k8 + 4 + tg]);
                    a[mt][3] = __float_as_uint(r1[k8 + 4 + tg]);
                }
#pragma unroll
                for (int g = 0; g < 4; g++) {
                    const float* wg = Ws + g * 8192 + (kc * 16 + k8) * 8;
                    unsigned bb[2];
                    bb[0] = __float_as_uint(wg[tg * 8 + gr]);
                    bb[1] = __float_as_uint(wg[(4 + tg) * 8 + gr]);
                    mma8(acc[g][0], a[0], bb);
                    mma8(acc[g][1], a[1], bb);
                }
            }
            if (kc + 3 < 64) fill(kc + 3);
            CP_COMMIT();
        }

        // ---- fused gate epilogue; c stays in registers ----
#pragma unroll
        for (int mt = 0; mt < 2; mt++)
#pragma unroll
            for (int hf = 0; hf < 2; hf++) {
                int m = mb + mt * 16 + hf * 8 + gr;
                const float* p = pt + (size_t)m * G4H + n0 + 2 * tg;
                float2 Pi = *(const float2*)(p);
                float2 Pf = *(const float2*)(p + H_);
                float2 Po = *(const float2*)(p + 2 * H_);
                float2 Pg = *(const float2*)(p + 3 * H_);
                float h2[2];
#pragma unroll
                for (int cc = 0; cc < 2; cc++) {
                    int r = hf * 2 + cc;
                    float pi = acc[0][mt][r] + (cc ? Pi.y : Pi.x);
                    float pfv = acc[1][mt][r] + (cc ? Pf.y : Pf.x);
                    float po = acc[2][mt][r] + (cc ? Po.y : Po.x);
                    float pg = acc[3][mt][r] + (cc ? Pg.y : Pg.x);
                    float c = sigmoidf_(pfv) * creg[mt][hf][cc] + sigmoidf_(pi) * tanhf(pg);
                    creg[mt][hf][cc] = c;
                    h2[cc] = sigmoidf_(po) * tanhf(c);
                }
                *(float2*)(hout + (size_t)m * H_ + n0 + 2 * tg) = make_float2(h2[0], h2[1]);
                *(float2*)(cout + (size_t)m * H_ + n0 + 2 * tg) =
                    make_float2(creg[mt][hf][0], creg[mt][hf][1]);
            }
#pragma unroll
        for (int g = 0; g < 4; g++)
#pragma unroll
            for (int mt = 0; mt < 2; mt++)
#pragma unroll
                for (int r = 0; r < 4; r++) acc[g][mt][r] = 0.0f;

        // ---- inter-CTA barrier ----
        __syncthreads();
        if (tid == 0) {
            __threadfence();
            atomicAdd(&g_bar, 1u);
            unsigned tgt = (unsigned)(t + 1) * SCAN_NCTA;
            while (atomicAdd(&g_bar, 0u) < tgt) __nanosleep(64);
            __threadfence();
        }
        __syncthreads();
    }
}

// ===========================================================================
// Kernel 5: layer-1 batch-parallel; 3-stage cp.async pipeline, K=2048.
// BM=128, 32 cols/gate; 8 warps (4M x 2N); 2 CTAs/SM.
// ===========================================================================
__global__ __launch_bounds__(256, 2) void k_lstm1(const float* __restrict__ wi1,
                                                  const float* __restrict__ wh1,
                                                  const float* __restrict__ bi1,
                                                  const float* __restrict__ bh1) {
    extern __shared__ float sm1[];
    float* As = sm1;                       // 3 x [128][36]
    float* Bs = sm1 + 3 * 128 * 36;        // 3 x [4*32][36]

    const int m0 = blockIdx.y * 128;
    const int n0 = blockIdx.x * 32;
    const int tid = threadIdx.x, lane = tid & 31, wid = tid >> 5;
    const int wm = wid & 3, wn = wid >> 2;
    const int tg = lane & 3, gr = lane >> 2;

    float acc[4][2][2][4];
#pragma unroll
    for (int g = 0; g < 4; g++)
#pragma unroll
        for (int mt = 0; mt < 2; mt++)
#pragma unroll
            for (int nt = 0; nt < 2; nt++)
#pragma unroll
                for (int r = 0; r < 4; r++) acc[g][mt][nt][r] = 0.0f;

    auto fill = [&](int kc) {
        int s = kc % 3;
        bool second = (kc >= 32);
        int kk0 = (kc * 32) & (H_ - 1);
        float* dA = As + s * 128 * 36;
        {
#pragma unroll
            for (int it = 0; it < 4; it++) {
                int idx = tid + it * 256, row = idx >> 3, q = idx & 7;
                int m = m0 + row, bq = m & 255;
                int msel = second ? (m - bq + 255 - bq) : m;
                cpa16(dA + row * 36 + q * 4, g_h0 + (size_t)msel * H_ + kk0 + q * 4);
            }
        }
        const float* W = second ? wh1 : wi1;
        float* dB = Bs + s * 128 * 36;
#pragma unroll
        for (int it = 0; it < 4; it++) {
            int idx = tid + it * 256;
            int g = idx >> 8, rem = idx & 255, row = rem >> 3, q = rem & 7;
            cpa16(dB + (g * 32 + row) * 36 + q * 4,
                  W + (size_t)(g * H_ + n0 + row) * H_ + kk0 + q * 4);
        }
    };

    fill(0); CP_COMMIT();
    fill(1); CP_COMMIT();

    for (int kc = 0; kc < 64; kc++) {
        cp_wait<1>();
        __syncthreads();
        const float* Ab = As + (kc % 3) * 128 * 36;
        const float* Bb = Bs + (kc % 3) * 128 * 36;
#pragma unroll
        for (int ks = 0; ks < 4; ks++) {
            const int k8 = ks * 8;
            unsigned a[2][4];
#pragma unroll
            for (int mt = 0; mt < 2; mt++) {
                const float* r0 = Ab + (wm * 32 + mt * 16 + gr) * 36;
                const float* r1 = r0 + 8 * 36;
                a[mt][0] = __float_as_uint(r0[k8 + tg]);
                a[mt][1] = __float_as_uint(r1[k8 + tg]);
                a[mt][2] = __float_as_uint(r0[k8 + 4 + tg]);
                a[mt][3] = __float_as_uint(r1[k8 + 4 + tg]);
            }
#pragma unroll
            for (int g = 0; g < 4; g++) {
#pragma unroll
                for (int nt = 0; nt < 2; nt++) {
                    const float* rb = Bb + (g * 32 + wn * 16 + nt * 8 + gr) * 36;
                    unsigned b[2];
                    b[0] = __float_as_uint(rb[k8 + tg]);
                    b[1] = __float_as_uint(rb[k8 + 4 + tg]);
                    mma8(acc[g][0][nt], a[0], b);
                    mma8(acc[g][1][nt], a[1], b);
                }
            }
        }
        if (kc + 2 < 64) fill(kc + 2);
        CP_COMMIT();
    }

#pragma unroll
    for (int mt = 0; mt < 2; mt++)
#pragma unroll
        for (int half = 0; half < 2; half++) {
            int m = m0 + wm * 32 + mt * 16 + half * 8 + gr;
            int bq = m & 255;
            int mflip = m - bq + 255 - bq;
            const float* cp = g_c0 + (size_t)mflip * H_;
            float* hp = g_h1 + (size_t)m * H_;
#pragma unroll
            for (int nt = 0; nt < 2; nt++)
#pragma unroll
                for (int cc = 0; cc < 2; cc++) {
                    int nn = n0 + wn * 16 + nt * 8 + 2 * tg + cc;
                    int r = half * 2 + cc;
                    float pi = acc[0][mt][nt][r] + bi1[nn] + bh1[nn];
                    float pf = acc[1][mt][nt][r] + bi1[H_ + nn] + bh1[H_ + nn];
                    float po = acc[2][mt][nt][r] + bi1[2 * H_ + nn] + bh1[2 * H_ + nn];
                    float pg = acc[3][mt][nt][r] + bi1[3 * H_ + nn] + bh1[3 * H_ + nn];
                    float c = sigmoidf_(pf) * cp[nn] + sigmoidf_(pi) * tanhf(pg);
                    hp[nn] = sigmoidf_(po) * tanhf(c);
                }
        }
}

// ===========================================================================
// Kernel 6: decode. out[m, c] = [h0[m] | h1[m]] . dec_w[c] + dec_b[c]
// ===========================================================================
__global__ __launch_bounds__(256) void k_decode(const float* __restrict__ dec_w,
                                                const float* __restrict__ dec_b,
                                                float* __restrict__ out) {
    int gwarp = (blockIdx.x * blockDim.x + threadIdx.x) >> 5;
    int lane = threadIdx.x & 31;
    if (gwarp >= M_) return;
    const float* h0r = g_h0 + (size_t)gwarp * H_;
    const float* h1r = g_h1 + (size_t)gwarp * H_;

    float acc[C_];
#pragma unroll
    for (int c = 0; c < C_; c++) acc[c] = 0.0f;

    for (int k = lane * 4; k < H_; k += 128) {
        float4 v0 = *(const float4*)(h0r + k);
        float4 v1 = *(const float4*)(h1r + k);
#pragma unroll
        for (int c = 0; c < C_; c++) {
            const float* w = dec_w + (size_t)c * 2 * H_;
            float4 w0 = *(const float4*)(w + k);
            float4 w1 = *(const float4*)(w + H_ + k);
            acc[c] += v0.x * w0.x + v0.y * w0.y + v0.z * w0.z + v0.w * w0.w
                    + v1.x * w1.x + v1.y * w1.y + v1.z * w1.z + v1.w * w1.w;
        }
    }
#pragma unroll
    for (int c = 0; c < C_; c++) {
#pragma unroll
        for (int off = 16; off > 0; off >>= 1)
            acc[c] += __shfl_down_sync(0xFFFFFFFFu, acc[c], off);
    }
    if (lane == 0) {
#pragma unroll
        for (int c = 0; c < C_; c++)
            out[(size_t)gwarp * C_ + c] = acc[c] + dec_b[c];
    }
}

// ===========================================================================
// Launch
// ===========================================================================
extern "C" void kernel_launch(void* const* d_in, const int* in_sizes, int n_in,
                              void* d_out, int out_size) {
    const int*   tokens = (const int*)d_in[0];
    const float* casing = (const float*)d_in[1];
    const float* pos    = (const float*)d_in[2];
    const float* emb    = (const float*)d_in[3];
    const float* wi0    = (const float*)d_in[4];
    const float* bi0    = (const float*)d_in[5];
    const float* wh0    = (const float*)d_in[6];
    const float* bh0    = (const float*)d_in[7];
    const float* wi1    = (const float*)d_in[8];
    const float* bi1    = (const float*)d_in[9];
    const float* wh1    = (const float*)d_in[10];
    const float* bh1    = (const float*)d_in[11];
    const float* dec_w  = (const float*)d_in[12];
    const float* dec_b  = (const float*)d_in[13];
    const float* h_init = (const float*)d_in[14];
    const float* c_init = (const float*)d_in[15];
    float* out = (float*)d_out;

    (void)in_sizes; (void)n_in; (void)out_size;

    cudaFuncSetAttribute(k_lstm0_scan, cudaFuncAttributeMaxDynamicSharedMemorySize,
                         SCAN_SMEM);
    cudaFuncSetAttribute(k_lstm1, cudaFuncAttributeMaxDynamicSharedMemorySize,
                         L1_SMEM);

    k_reset<<<1, 1>>>();
    k_build_x<<<M_, 256>>>(tokens, casing, pos, emb);
    k_pad_wi0<<<G4H, 256>>>(wi0);
    k_gemm_pre0<<<dim3(G4H / 128, M_ / 128), 256>>>(bi0, bh0);
    k_lstm0_scan<<<SCAN_NCTA, 256, SCAN_SMEM>>>(h_init, c_init, wh0);
    k_lstm1<<<dim3(H_ / 32, M_ / 128), 256, L1_SMEM>>>(wi1, wh1, bi1, bh1);
    k_decode<<<(M_ * 32) / 256, 256>>>(dec_w, dec_b, out);
}